// round 6
// baseline (speedup 1.0000x reference)
#include <cuda_runtime.h>

#define PRED_D 90   // B*5 + C
#define TGT_D 85    // 5 + C
#define THREADS 128
#define TILE 128
#define NWARPS 4
#define CHUNK 48
#define CELL_B 712  // smem bytes per gathered cell: 360 pred + 340 tgt + 12 pad (stride 178 floats, gcd(178,32)=2)

// Accumulators: [0]=xy [1]=wh [2]=conf_obj [3]=conf_noobj [4]=class
__device__ double g_acc[5];
__device__ unsigned int g_done;

__device__ __forceinline__ void cpa8(unsigned dst, const void* src) {
    asm volatile("cp.async.ca.shared.global [%0], [%1], 8;\n" :: "r"(dst), "l"(src));
}
__device__ __forceinline__ void cpa4(unsigned dst, const void* src) {
    asm volatile("cp.async.ca.shared.global [%0], [%1], 4;\n" :: "r"(dst), "l"(src));
}

__device__ __forceinline__ float iou_vs(
    float tx1, float ty1, float tx2, float ty2,
    float px, float py, float pw, float ph,
    float fi, float fj)
{
    const float invS = 1.0f / 7.0f;
    float xc = (px + fj) * invS;
    float yc = (py + fi) * invS;
    float x1 = xc - pw * 0.5f, x2 = xc + pw * 0.5f;
    float y1 = yc - ph * 0.5f, y2 = yc + ph * 0.5f;
    float iw = fmaxf(fminf(tx2, x2) - fmaxf(tx1, x1), 0.0f);
    float ih = fmaxf(fminf(ty2, y2) - fmaxf(ty1, y1), 0.0f);
    float inter = iw * ih;
    float area_a = (tx2 - tx1) * (ty2 - ty1);
    float area_b = (x2 - x1) * (y2 - y1);
    return inter / (area_a + area_b - inter + 1e-6f);
}

__global__ void __launch_bounds__(THREADS)
yolo_loss_kernel(const float* __restrict__ pred,
                 const float* __restrict__ tgt,
                 int ncells, float* __restrict__ out, double inv_bs)
{
    __shared__ __align__(16) char s_buf[CHUNK * CELL_B];
    __shared__ int   s_list[TILE];
    __shared__ int   s_cnt;
    __shared__ float s_red[5][NWARPS];
    __shared__ bool  s_last;

    const int tid  = threadIdx.x;
    const int lane = tid & 31;
    const int wid  = tid >> 5;

    if (tid == 0) s_cnt = 0;
    __syncthreads();

    const int cell0 = blockIdx.x * TILE + tid;

    float a_cn = 0.0f;

    // ---------------- Phase 1: scan + noobj loss + ballot compaction ------
    {
        float tc = 0.0f, pc = 0.0f;
        bool valid = (cell0 < ncells);
        if (valid) {
            tc = __ldg(&tgt[(long long)cell0 * TGT_D + 4]);
            pc = __ldg(&pred[(long long)cell0 * PRED_D + 9]);
        }
        bool isobj = valid && (tc != 0.0f);
        if (valid && !isobj) a_cn += pc * pc;

        unsigned int m = __ballot_sync(0xffffffffu, isobj);
        int nwobj = __popc(m);
        int wbase = 0;
        if (lane == 0 && nwobj > 0) wbase = atomicAdd(&s_cnt, nwobj);
        wbase = __shfl_sync(0xffffffffu, wbase, 0);
        if (isobj) {
            int pos = wbase + __popc(m & ((1u << lane) - 1u));
            s_list[pos] = cell0;
        }
    }
    __syncthreads();

    const int nobj = s_cnt;

    float a_xy = 0.0f, a_wh = 0.0f, a_co = 0.0f, a_cls = 0.0f;

    const unsigned sbase = (unsigned)__cvta_generic_to_shared(s_buf);

    // ---------------- Phase 2: gather full rows via cp.async, compute -----
    for (int cb = 0; cb < nobj; cb += CHUNK) {
        const int nch = min(CHUNK, nobj - cb);

        // ---- gather: warp-per-cell ----
        for (int s = wid; s < nch; s += NWARPS) {
            const int cell = s_list[cb + s];
            const char* psrc = (const char*)pred + (long long)cell * (PRED_D * 4);
            const char* tsrc = (const char*)tgt  + (long long)cell * (TGT_D * 4);
            const unsigned dst = sbase + s * CELL_B;

            // pred row: 360 B = 45 x 8B chunks
            cpa8(dst + lane * 8, psrc + lane * 8);
            if (lane < 13) cpa8(dst + (32 + lane) * 8, psrc + (32 + lane) * 8);
            // tgt row: 340 B = 85 x 4B chunks, stored at +360
            cpa4(dst + 360 + lane * 4, tsrc + lane * 4);
            cpa4(dst + 360 + (32 + lane) * 4, tsrc + (32 + lane) * 4);
            if (lane < 21) cpa4(dst + 360 + (64 + lane) * 4, tsrc + (64 + lane) * 4);
        }
        asm volatile("cp.async.commit_group;\n" ::: "memory");
        asm volatile("cp.async.wait_group 0;\n" ::: "memory");
        __syncthreads();

        // ---- box losses: thread-per-cell, all from smem ----
        for (int s = tid; s < nch; s += THREADS) {
            const float* row = (const float*)(s_buf + s * CELL_B);
            const int cell = s_list[cb + s];

            float p0 = row[0], p1 = row[1], p2 = row[2], p3 = row[3];
            float p5 = row[5], p6 = row[6], p7 = row[7], p8 = row[8], p9 = row[9];
            float t0 = row[90], t1 = row[91], t2 = row[92], t3 = row[93], t4 = row[94];

            const int ij = cell % 49;
            const float fi = (float)(ij / 7);
            const float fj = (float)(ij % 7);

            const float invS = 1.0f / 7.0f;
            float txc = (t0 + fj) * invS;
            float tyc = (t1 + fi) * invS;
            float tx1 = txc - t2 * 0.5f, tx2c = txc + t2 * 0.5f;
            float ty1 = tyc - t3 * 0.5f, ty2c = tyc + t3 * 0.5f;

            float iou0 = iou_vs(tx1, ty1, tx2c, ty2c, p0, p1, p2, p3, fi, fj);
            float iou1 = iou_vs(tx1, ty1, tx2c, ty2c, p5, p6, p7, p8, fi, fj);

            bool sel = (iou0 > iou1);
            float sx = sel ? p5 : p0;
            float sy = sel ? p6 : p1;
            float sw = sel ? p7 : p2;
            float sh = sel ? p8 : p3;

            float dx = t0 - sx, dy = t1 - sy;
            a_xy += dx * dx + dy * dy;

            float dw = sqrtf(t2) - sqrtf(fmaxf(sw, 0.0f));
            float dh = sqrtf(t3) - sqrtf(fmaxf(sh, 0.0f));
            a_wh += dw * dw + dh * dh;

            float dc = t4 - p9;
            a_co += dc * dc;
        }

        // ---- class loss: warp-per-cell, all from smem ----
        for (int s = wid; s < nch; s += NWARPS) {
            const float* row = (const float*)(s_buf + s * CELL_B);
            // pred class: floats 10..89; tgt class: floats 95..174
            float d0 = row[95 + lane] - row[10 + lane];
            float d1 = row[127 + lane] - row[42 + lane];
            float acc = d0 * d0 + d1 * d1;
            if (lane < 16) {
                float d2 = row[159 + lane] - row[74 + lane];
                acc += d2 * d2;
            }
            a_cls += acc;
        }
        __syncthreads();   // protect s_buf before next chunk's gather
    }

    // ---------------- Reduction ----------------
    #pragma unroll
    for (int off = 16; off > 0; off >>= 1) {
        a_xy  += __shfl_xor_sync(0xffffffffu, a_xy,  off);
        a_wh  += __shfl_xor_sync(0xffffffffu, a_wh,  off);
        a_co  += __shfl_xor_sync(0xffffffffu, a_co,  off);
        a_cn  += __shfl_xor_sync(0xffffffffu, a_cn,  off);
        a_cls += __shfl_xor_sync(0xffffffffu, a_cls, off);
    }

    if (lane == 0) {
        s_red[0][wid] = a_xy;
        s_red[1][wid] = a_wh;
        s_red[2][wid] = a_co;
        s_red[3][wid] = a_cn;
        s_red[4][wid] = a_cls;
    }
    __syncthreads();

    if (tid < 5) {
        double sum = 0.0;
        #pragma unroll
        for (int w = 0; w < NWARPS; w++) sum += (double)s_red[tid][w];
        atomicAdd(&g_acc[tid], sum);
    }
    __syncthreads();

    // ---------------- Last block finalizes + resets ----------------
    if (tid == 0) {
        __threadfence();
        unsigned int t = atomicAdd(&g_done, 1u);
        s_last = (t == gridDim.x - 1);
    }
    __syncthreads();

    if (s_last && tid == 0) {
        __threadfence();
        double lxy  = atomicAdd(&g_acc[0], 0.0) * inv_bs;
        double lwh  = atomicAdd(&g_acc[1], 0.0) * inv_bs;
        double lco  = atomicAdd(&g_acc[2], 0.0) * inv_bs;
        double lcn  = atomicAdd(&g_acc[3], 0.0) * inv_bs;
        double lcls = atomicAdd(&g_acc[4], 0.0) * inv_bs;
        double loss = (5.0 * lxy + 5.0 * lwh + lco + 0.5 * lcn + lcls) * inv_bs;
        out[0] = (float)loss;
        out[1] = (float)lxy;
        out[2] = (float)lwh;
        out[3] = (float)lco;
        out[4] = (float)lcn;
        out[5] = (float)lcls;
        g_acc[0] = 0.0; g_acc[1] = 0.0; g_acc[2] = 0.0;
        g_acc[3] = 0.0; g_acc[4] = 0.0;
        __threadfence();
        g_done = 0u;
    }
}

extern "C" void kernel_launch(void* const* d_in, const int* in_sizes, int n_in,
                              void* d_out, int out_size)
{
    const float* pred = (const float*)d_in[0];
    const float* tgt  = (const float*)d_in[1];
    float* out = (float*)d_out;

    const int N = in_sizes[0] / (49 * PRED_D);
    const int ncells = N * 49;
    const int blocks = (ncells + TILE - 1) / TILE;

    yolo_loss_kernel<<<blocks, THREADS>>>(pred, tgt, ncells, out, 1.0 / (double)N);
}

// round 7
// speedup vs baseline: 1.3089x; 1.3089x over previous
#include <cuda_runtime.h>

#define PRED_D 90   // B*5 + C
#define TGT_D 85    // 5 + C
#define THREADS 256
#define TILE 256
#define NWARPS (THREADS / 32)

// Accumulators: [0]=xy [1]=wh [2]=conf_obj [3]=conf_noobj [4]=class
__device__ double g_acc[5];
__device__ unsigned int g_done;

struct ClsLd {
    float2 pa, pb;          // pred class chunks
    float  pe;
    float  ta0, ta1, tb0, tb1, te;   // tgt class
};

__device__ __forceinline__ void load_cls(const float* __restrict__ pred,
                                         const float* __restrict__ tgt,
                                         int cell, int hl, ClsLd& r)
{
    const long long bp = (long long)cell * PRED_D;
    const long long bt = (long long)cell * TGT_D;
    // bp even -> bp+10+2hl even -> 8B aligned float2 OK
    r.pa  = __ldg((const float2*)(pred + bp + 10 + 2 * hl));
    r.pb  = __ldg((const float2*)(pred + bp + 42 + 2 * hl));
    r.pe  = __ldg(pred + bp + 74 + hl);
    r.ta0 = __ldg(tgt + bt + 5 + 2 * hl);
    r.ta1 = __ldg(tgt + bt + 6 + 2 * hl);
    r.tb0 = __ldg(tgt + bt + 37 + 2 * hl);
    r.tb1 = __ldg(tgt + bt + 38 + 2 * hl);
    r.te  = __ldg(tgt + bt + 69 + hl);
}

__device__ __forceinline__ float iou_vs(
    float tx1, float ty1, float tx2, float ty2,
    float px, float py, float pw, float ph,
    float fi, float fj)
{
    const float invS = 1.0f / 7.0f;
    float xc = (px + fj) * invS;
    float yc = (py + fi) * invS;
    float x1 = xc - pw * 0.5f, x2 = xc + pw * 0.5f;
    float y1 = yc - ph * 0.5f, y2 = yc + ph * 0.5f;
    float iw = fmaxf(fminf(tx2, x2) - fmaxf(tx1, x1), 0.0f);
    float ih = fmaxf(fminf(ty2, y2) - fmaxf(ty1, y1), 0.0f);
    float inter = iw * ih;
    float area_a = (tx2 - tx1) * (ty2 - ty1);
    float area_b = (x2 - x1) * (y2 - y1);
    return inter / (area_a + area_b - inter + 1e-6f);
}

__global__ void __launch_bounds__(THREADS)
yolo_loss_kernel(const float* __restrict__ pred,
                 const float* __restrict__ tgt,
                 int ncells, float* __restrict__ out, double inv_bs)
{
    __shared__ int   s_list[TILE];
    __shared__ int   s_cnt;
    __shared__ float s_red[5][NWARPS];
    __shared__ bool  s_last;

    const int tid  = threadIdx.x;
    const int lane = tid & 31;
    const int wid  = tid >> 5;

    if (tid == 0) s_cnt = 0;
    __syncthreads();

    const int cell0 = blockIdx.x * TILE + tid;

    float a_cn = 0.0f;

    // ---------------- Phase 1: scan + noobj loss + ballot compaction ------
    {
        float tc = 0.0f, pc = 0.0f;
        bool valid = (cell0 < ncells);
        if (valid) {
            tc = __ldg(&tgt[(long long)cell0 * TGT_D + 4]);
            pc = __ldg(&pred[(long long)cell0 * PRED_D + 9]);
        }
        bool isobj = valid && (tc != 0.0f);
        if (valid && !isobj) a_cn += pc * pc;

        unsigned int m = __ballot_sync(0xffffffffu, isobj);
        int nwobj = __popc(m);
        int wbase = 0;
        if (lane == 0 && nwobj > 0) wbase = atomicAdd(&s_cnt, nwobj);
        wbase = __shfl_sync(0xffffffffu, wbase, 0);
        if (isobj) {
            int pos = wbase + __popc(m & ((1u << lane) - 1u));
            s_list[pos] = cell0;
        }
    }
    __syncthreads();

    const int nobj = s_cnt;

    float a_xy = 0.0f, a_wh = 0.0f, a_co = 0.0f, a_cls = 0.0f;

    // ---------------- Phase 2a: box losses, thread-per-object-cell --------
    // pred row stride 360B (8-aligned) -> float2 loads OK; tgt 4-aligned -> scalar.
    for (int k = tid; k < nobj; k += THREADS) {
        const int cell = s_list[k];
        const long long bp = (long long)cell * PRED_D;
        const long long bt = (long long)cell * TGT_D;

        float2 b0 = __ldg((const float2*)(pred + bp));       // p0,p1
        float2 b1 = __ldg((const float2*)(pred + bp + 2));   // p2,p3
        float2 b2 = __ldg((const float2*)(pred + bp + 4));   // p4,p5
        float2 b3 = __ldg((const float2*)(pred + bp + 6));   // p6,p7
        float2 b4 = __ldg((const float2*)(pred + bp + 8));   // p8,p9
        float t0 = __ldg(&tgt[bt + 0]);
        float t1 = __ldg(&tgt[bt + 1]);
        float t2 = __ldg(&tgt[bt + 2]);
        float t3 = __ldg(&tgt[bt + 3]);
        float t4 = __ldg(&tgt[bt + 4]);

        const int ij = cell % 49;
        const float fi = (float)(ij / 7);
        const float fj = (float)(ij % 7);

        const float invS = 1.0f / 7.0f;
        float txc = (t0 + fj) * invS;
        float tyc = (t1 + fi) * invS;
        float tx1 = txc - t2 * 0.5f, tx2c = txc + t2 * 0.5f;
        float ty1 = tyc - t3 * 0.5f, ty2c = tyc + t3 * 0.5f;

        float iou0 = iou_vs(tx1, ty1, tx2c, ty2c, b0.x, b0.y, b1.x, b1.y, fi, fj);
        float iou1 = iou_vs(tx1, ty1, tx2c, ty2c, b2.y, b3.x, b3.y, b4.x, fi, fj);

        bool sel = (iou0 > iou1);   // true -> second box
        float sx = sel ? b2.y : b0.x;
        float sy = sel ? b3.x : b0.y;
        float sw = sel ? b3.y : b1.x;
        float sh = sel ? b4.x : b1.y;

        float dx = t0 - sx, dy = t1 - sy;
        a_xy += dx * dx + dy * dy;

        float dw = sqrtf(t2) - sqrtf(fmaxf(sw, 0.0f));
        float dh = sqrtf(t3) - sqrtf(fmaxf(sh, 0.0f));
        a_wh += dw * dw + dh * dh;

        float dc = t4 - b4.y;
        a_co += dc * dc;
    }

    // ---------------- Phase 2b: class loss, HALF-warp-per-cell, pipelined -
    {
        const int hw = lane >> 4;     // half-warp id: 0 or 1
        const int hl = lane & 15;     // lane within half-warp
        const int kstride = NWARPS * 2;

        int k = wid * 2 + hw;
        int cell = (k < nobj) ? s_list[k] : -1;
        ClsLd cur = {};
        if (cell >= 0) load_cls(pred, tgt, cell, hl, cur);

        while (cell >= 0) {
            int kn = k + kstride;
            int ncell = (kn < nobj) ? s_list[kn] : -1;
            ClsLd nxt = {};
            if (ncell >= 0) load_cls(pred, tgt, ncell, hl, nxt);

            float d0 = cur.ta0 - cur.pa.x;
            float d1 = cur.ta1 - cur.pa.y;
            float d2 = cur.tb0 - cur.pb.x;
            float d3 = cur.tb1 - cur.pb.y;
            float d4 = cur.te  - cur.pe;
            a_cls += d0 * d0 + d1 * d1 + d2 * d2 + d3 * d3 + d4 * d4;

            cur = nxt;
            cell = ncell;
            k = kn;
        }
    }

    // ---------------- Reduction ----------------
    #pragma unroll
    for (int off = 16; off > 0; off >>= 1) {
        a_xy  += __shfl_xor_sync(0xffffffffu, a_xy,  off);
        a_wh  += __shfl_xor_sync(0xffffffffu, a_wh,  off);
        a_co  += __shfl_xor_sync(0xffffffffu, a_co,  off);
        a_cn  += __shfl_xor_sync(0xffffffffu, a_cn,  off);
        a_cls += __shfl_xor_sync(0xffffffffu, a_cls, off);
    }

    if (lane == 0) {
        s_red[0][wid] = a_xy;
        s_red[1][wid] = a_wh;
        s_red[2][wid] = a_co;
        s_red[3][wid] = a_cn;
        s_red[4][wid] = a_cls;
    }
    __syncthreads();

    if (tid < 5) {
        double sum = 0.0;
        #pragma unroll
        for (int w = 0; w < NWARPS; w++) sum += (double)s_red[tid][w];
        atomicAdd(&g_acc[tid], sum);
    }
    __syncthreads();

    // ---------------- Last block finalizes + resets ----------------
    if (tid == 0) {
        __threadfence();
        unsigned int t = atomicAdd(&g_done, 1u);
        s_last = (t == gridDim.x - 1);
    }
    __syncthreads();

    if (s_last && tid == 0) {
        __threadfence();
        double lxy  = atomicAdd(&g_acc[0], 0.0) * inv_bs;
        double lwh  = atomicAdd(&g_acc[1], 0.0) * inv_bs;
        double lco  = atomicAdd(&g_acc[2], 0.0) * inv_bs;
        double lcn  = atomicAdd(&g_acc[3], 0.0) * inv_bs;
        double lcls = atomicAdd(&g_acc[4], 0.0) * inv_bs;
        double loss = (5.0 * lxy + 5.0 * lwh + lco + 0.5 * lcn + lcls) * inv_bs;
        out[0] = (float)loss;
        out[1] = (float)lxy;
        out[2] = (float)lwh;
        out[3] = (float)lco;
        out[4] = (float)lcn;
        out[5] = (float)lcls;
        g_acc[0] = 0.0; g_acc[1] = 0.0; g_acc[2] = 0.0;
        g_acc[3] = 0.0; g_acc[4] = 0.0;
        __threadfence();
        g_done = 0u;
    }
}

extern "C" void kernel_launch(void* const* d_in, const int* in_sizes, int n_in,
                              void* d_out, int out_size)
{
    const float* pred = (const float*)d_in[0];
    const float* tgt  = (const float*)d_in[1];
    float* out = (float*)d_out;

    const int N = in_sizes[0] / (49 * PRED_D);
    const int ncells = N * 49;
    const int blocks = (ncells + TILE - 1) / TILE;

    yolo_loss_kernel<<<blocks, THREADS>>>(pred, tgt, ncells, out, 1.0 / (double)N);
}

// round 8
// speedup vs baseline: 1.3955x; 1.0662x over previous
#include <cuda_runtime.h>

#define PRED_D 90   // B*5 + C
#define TGT_D 85    // 5 + C
#define THREADS 256
#define TILE 512
#define PERT (TILE / THREADS)
#define NWARPS (THREADS / 32)
#define QSTRIDE (NWARPS * 4)

// Accumulators: [0]=xy [1]=wh [2]=conf_obj [3]=conf_noobj [4]=class
__device__ double g_acc[5];
__device__ unsigned int g_done;

// Quarter-warp class load: lane ql (0..7) covers class pairs {2ql,2ql+1}+16k, k=0..4
struct QLd {
    float2 pa[5];
    float  tg[10];
};

__device__ __forceinline__ void load_cls(const float* __restrict__ pred,
                                         const float* __restrict__ tgt,
                                         int cell, int ql, QLd& r)
{
    const long long bp = (long long)cell * PRED_D;
    const long long bt = (long long)cell * TGT_D;
    #pragma unroll
    for (int k = 0; k < 5; k++)
        r.pa[k] = __ldg((const float2*)(pred + bp + 10 + 16 * k + 2 * ql));
    #pragma unroll
    for (int k = 0; k < 5; k++) {
        r.tg[2 * k]     = __ldg(tgt + bt + 5 + 16 * k + 2 * ql);
        r.tg[2 * k + 1] = __ldg(tgt + bt + 6 + 16 * k + 2 * ql);
    }
}

__device__ __forceinline__ float consume_cls(const QLd& r)
{
    float acc = 0.0f;
    #pragma unroll
    for (int k = 0; k < 5; k++) {
        float d0 = r.tg[2 * k]     - r.pa[k].x;
        float d1 = r.tg[2 * k + 1] - r.pa[k].y;
        acc += d0 * d0 + d1 * d1;
    }
    return acc;
}

__device__ __forceinline__ float iou_vs(
    float tx1, float ty1, float tx2, float ty2,
    float px, float py, float pw, float ph,
    float fi, float fj)
{
    const float invS = 1.0f / 7.0f;
    float xc = (px + fj) * invS;
    float yc = (py + fi) * invS;
    float x1 = xc - pw * 0.5f, x2 = xc + pw * 0.5f;
    float y1 = yc - ph * 0.5f, y2 = yc + ph * 0.5f;
    float iw = fmaxf(fminf(tx2, x2) - fmaxf(tx1, x1), 0.0f);
    float ih = fmaxf(fminf(ty2, y2) - fmaxf(ty1, y1), 0.0f);
    float inter = iw * ih;
    float area_a = (tx2 - tx1) * (ty2 - ty1);
    float area_b = (x2 - x1) * (y2 - y1);
    return inter / (area_a + area_b - inter + 1e-6f);
}

__global__ void __launch_bounds__(THREADS)
yolo_loss_kernel(const float* __restrict__ pred,
                 const float* __restrict__ tgt,
                 int ncells, float* __restrict__ out, double inv_bs)
{
    __shared__ int   s_list[TILE];
    __shared__ int   s_cnt;
    __shared__ float s_red[5][NWARPS];
    __shared__ bool  s_last;

    const int tid  = threadIdx.x;
    const int lane = tid & 31;
    const int wid  = tid >> 5;

    if (tid == 0) s_cnt = 0;
    __syncthreads();

    float a_cn = 0.0f;

    // ---------------- Phase 1: scan + noobj loss + ballot compaction ------
    {
        float tc_v[PERT], pc_v[PERT];
        #pragma unroll
        for (int p = 0; p < PERT; p++) {
            int cell = blockIdx.x * TILE + p * THREADS + tid;
            tc_v[p] = 0.0f;
            pc_v[p] = 0.0f;
            if (cell < ncells) {
                tc_v[p] = __ldg(&tgt[(long long)cell * TGT_D + 4]);
                pc_v[p] = __ldg(&pred[(long long)cell * PRED_D + 9]);
            }
        }
        #pragma unroll
        for (int p = 0; p < PERT; p++) {
            int cell = blockIdx.x * TILE + p * THREADS + tid;
            bool valid = (cell < ncells);
            bool isobj = valid && (tc_v[p] != 0.0f);
            if (valid && !isobj) a_cn += pc_v[p] * pc_v[p];

            unsigned int m = __ballot_sync(0xffffffffu, isobj);
            int nwobj = __popc(m);
            int wbase = 0;
            if (lane == 0 && nwobj > 0) wbase = atomicAdd(&s_cnt, nwobj);
            wbase = __shfl_sync(0xffffffffu, wbase, 0);
            if (isobj) {
                int pos = wbase + __popc(m & ((1u << lane) - 1u));
                s_list[pos] = cell;
            }
        }
    }
    __syncthreads();

    const int nobj = s_cnt;

    float a_xy = 0.0f, a_wh = 0.0f, a_co = 0.0f, a_cls = 0.0f;

    // ---------------- Phase 2a: box losses, thread-per-object-cell --------
    // pred row stride 360B (8-aligned) -> float2 OK; tgt 4-aligned -> scalar.
    for (int k = tid; k < nobj; k += THREADS) {
        const int cell = s_list[k];
        const long long bp = (long long)cell * PRED_D;
        const long long bt = (long long)cell * TGT_D;

        float2 b0 = __ldg((const float2*)(pred + bp));       // p0,p1
        float2 b1 = __ldg((const float2*)(pred + bp + 2));   // p2,p3
        float2 b2 = __ldg((const float2*)(pred + bp + 4));   // p4,p5
        float2 b3 = __ldg((const float2*)(pred + bp + 6));   // p6,p7
        float2 b4 = __ldg((const float2*)(pred + bp + 8));   // p8,p9
        float t0 = __ldg(&tgt[bt + 0]);
        float t1 = __ldg(&tgt[bt + 1]);
        float t2 = __ldg(&tgt[bt + 2]);
        float t3 = __ldg(&tgt[bt + 3]);
        float t4 = __ldg(&tgt[bt + 4]);

        const int ij = cell % 49;
        const float fi = (float)(ij / 7);
        const float fj = (float)(ij % 7);

        const float invS = 1.0f / 7.0f;
        float txc = (t0 + fj) * invS;
        float tyc = (t1 + fi) * invS;
        float tx1 = txc - t2 * 0.5f, tx2c = txc + t2 * 0.5f;
        float ty1 = tyc - t3 * 0.5f, ty2c = tyc + t3 * 0.5f;

        float iou0 = iou_vs(tx1, ty1, tx2c, ty2c, b0.x, b0.y, b1.x, b1.y, fi, fj);
        float iou1 = iou_vs(tx1, ty1, tx2c, ty2c, b2.y, b3.x, b3.y, b4.x, fi, fj);

        bool sel = (iou0 > iou1);   // true -> second box
        float sx = sel ? b2.y : b0.x;
        float sy = sel ? b3.x : b0.y;
        float sw = sel ? b3.y : b1.x;
        float sh = sel ? b4.x : b1.y;

        float dx = t0 - sx, dy = t1 - sy;
        a_xy += dx * dx + dy * dy;

        float dw = sqrtf(t2) - sqrtf(fmaxf(sw, 0.0f));
        float dh = sqrtf(t3) - sqrtf(fmaxf(sh, 0.0f));
        a_wh += dw * dw + dh * dh;

        float dc = t4 - b4.y;
        a_co += dc * dc;
    }

    // ---------------- Phase 2b: class loss, QUARTER-warp-per-cell ---------
    {
        const int qw = lane >> 3;     // quarter-warp id 0..3
        const int ql = lane & 7;      // lane within quarter

        int k = wid * 4 + qw;
        int cell = (k < nobj) ? s_list[k] : -1;
        QLd cur;
        if (cell >= 0) load_cls(pred, tgt, cell, ql, cur);

        while (cell >= 0) {
            int kn = k + QSTRIDE;
            int ncell = (kn < nobj) ? s_list[kn] : -1;
            QLd nxt;
            if (ncell >= 0) load_cls(pred, tgt, ncell, ql, nxt);

            a_cls += consume_cls(cur);

            cur = nxt;
            cell = ncell;
            k = kn;
        }
    }

    // ---------------- Reduction ----------------
    #pragma unroll
    for (int off = 16; off > 0; off >>= 1) {
        a_xy  += __shfl_xor_sync(0xffffffffu, a_xy,  off);
        a_wh  += __shfl_xor_sync(0xffffffffu, a_wh,  off);
        a_co  += __shfl_xor_sync(0xffffffffu, a_co,  off);
        a_cn  += __shfl_xor_sync(0xffffffffu, a_cn,  off);
        a_cls += __shfl_xor_sync(0xffffffffu, a_cls, off);
    }

    if (lane == 0) {
        s_red[0][wid] = a_xy;
        s_red[1][wid] = a_wh;
        s_red[2][wid] = a_co;
        s_red[3][wid] = a_cn;
        s_red[4][wid] = a_cls;
    }
    __syncthreads();

    if (tid < 5) {
        double sum = 0.0;
        #pragma unroll
        for (int w = 0; w < NWARPS; w++) sum += (double)s_red[tid][w];
        atomicAdd(&g_acc[tid], sum);
    }
    __syncthreads();

    // ---------------- Last block finalizes + resets ----------------
    if (tid == 0) {
        __threadfence();
        unsigned int t = atomicAdd(&g_done, 1u);
        s_last = (t == gridDim.x - 1);
    }
    __syncthreads();

    if (s_last && tid == 0) {
        __threadfence();
        double lxy  = atomicAdd(&g_acc[0], 0.0) * inv_bs;
        double lwh  = atomicAdd(&g_acc[1], 0.0) * inv_bs;
        double lco  = atomicAdd(&g_acc[2], 0.0) * inv_bs;
        double lcn  = atomicAdd(&g_acc[3], 0.0) * inv_bs;
        double lcls = atomicAdd(&g_acc[4], 0.0) * inv_bs;
        double loss = (5.0 * lxy + 5.0 * lwh + lco + 0.5 * lcn + lcls) * inv_bs;
        out[0] = (float)loss;
        out[1] = (float)lxy;
        out[2] = (float)lwh;
        out[3] = (float)lco;
        out[4] = (float)lcn;
        out[5] = (float)lcls;
        g_acc[0] = 0.0; g_acc[1] = 0.0; g_acc[2] = 0.0;
        g_acc[3] = 0.0; g_acc[4] = 0.0;
        __threadfence();
        g_done = 0u;
    }
}

extern "C" void kernel_launch(void* const* d_in, const int* in_sizes, int n_in,
                              void* d_out, int out_size)
{
    const float* pred = (const float*)d_in[0];
    const float* tgt  = (const float*)d_in[1];
    float* out = (float*)d_out;

    const int N = in_sizes[0] / (49 * PRED_D);
    const int ncells = N * 49;
    const int blocks = (ncells + TILE - 1) / TILE;

    yolo_loss_kernel<<<blocks, THREADS>>>(pred, tgt, ncells, out, 1.0 / (double)N);
}